// round 1
// baseline (speedup 1.0000x reference)
#include <cuda_runtime.h>

// LatentODE2: B=8192, T=100, D=16, H=32, Hd=50, 2H=64, 10 Euler steps per t.
// Warp-cooperative design: 1 warp handles 4 batch elements (E=4).
// Lane j owns outputs {j, j+32} of each layer. Weights in SMEM, transposed and
// packed as float2 (output pairs) so one LDS.64 feeds 8 FMAs (2 outs x 4 elems).
// State h / z1 / x live in per-warp SMEM as float4 (one component per element),
// read via broadcast LDS.128 (conflict-free, 1 phase).

#define T_STEPS     100
#define D_IN        16
#define H_DIM       32
#define HD_DIM      50
#define EULER_STEPS 10
#define STEP_F      0.1f
#define DT_SCALER_F (1.0f / 24.0f)

#define NWARP       2
#define CTA_THREADS (NWARP * 32)
#define E_PER_WARP  4
#define N_ELEMS     8192
#define GRID_BLOCKS (N_ELEMS / (NWARP * E_PER_WARP))   // 1024

__device__ __forceinline__ float my_tanh(float v) {
    // tanh(v) = (e^{2v} - 1) / (e^{2v} + 1); clamp keeps e finite.
    v = fminf(fmaxf(v, -15.0f), 15.0f);
    float e = __expf(2.0f * v);
    return __fdividef(e - 1.0f, e + 1.0f);
}

__device__ __forceinline__ void fma4(float4& a, const float4 v, const float w) {
    a.x = fmaf(v.x, w, a.x);
    a.y = fmaf(v.y, w, a.y);
    a.z = fmaf(v.z, w, a.z);
    a.w = fmaf(v.w, w, a.w);
}

__global__ void __launch_bounds__(CTA_THREADS, 7)
latentode2_kernel(const float* __restrict__ dt,
                  const float* __restrict__ x,
                  const float* __restrict__ W1, const float* __restrict__ b1,
                  const float* __restrict__ W2, const float* __restrict__ b2,
                  const float* __restrict__ W3, const float* __restrict__ b3,
                  const float* __restrict__ W4, const float* __restrict__ b4,
                  float* __restrict__ out)
{
    // Packed weights:
    //   sW1[k*32+j] = (W1[j][k], W1[j+32][k])   k<48, j<32 (second half 0-padded past Hd)
    //   sW3[k*32+l] = (W3[l][k], W3[l+32][k])   k<32, l<32
    //   sW2[j*32+k] = W2[k][j]                  j<50, k<32
    __shared__ float2 sW1[48 * 32];
    __shared__ float2 sW3[32 * 32];
    __shared__ float  sW2[50 * 32];
    __shared__ float4 sH[NWARP][32];
    __shared__ float4 sZ[NWARP][52];
    __shared__ float4 sX[NWARP][16];

    const int tid = threadIdx.x;

    for (int idx = tid; idx < 48 * 32; idx += CTA_THREADS) {
        int k = idx >> 5, j = idx & 31;
        float a = W1[j * 48 + k];
        float b = (j + 32 < HD_DIM) ? W1[(j + 32) * 48 + k] : 0.0f;
        sW1[idx] = make_float2(a, b);
    }
    for (int idx = tid; idx < 32 * 32; idx += CTA_THREADS) {
        int k = idx >> 5, l = idx & 31;
        sW3[idx] = make_float2(W3[l * 32 + k], W3[(l + 32) * 32 + k]);
    }
    for (int idx = tid; idx < 50 * 32; idx += CTA_THREADS) {
        int j = idx >> 5, k = idx & 31;
        sW2[idx] = W2[k * 50 + j];
    }
    __syncthreads();

    const int warp = tid >> 5;
    const int lane = tid & 31;
    const int e0   = (blockIdx.x * NWARP + warp) * E_PER_WARP;

    // Per-lane constants.
    const float b1a = b1[lane];
    const float b1b = (lane + 32 < HD_DIM) ? b1[lane + 32] : 0.0f;
    const float b2o = b2[lane];
    const float b3a = b3[lane];
    const float b3b = b3[lane + 32];
    const float b4v = b4[0];
    const float w4a = W4[lane];
    const float w4b = W4[lane + 32];

    float4* hsh = sH[warp];
    float4* zsh = sZ[warp];
    float4* xsh = sX[warp];

    float4 h4 = make_float4(0.0f, 0.0f, 0.0f, 0.0f);
    hsh[lane] = h4;
    __syncwarp();

    const float2* dt2 = (const float2*)dt;

#pragma unroll 1
    for (int t = 0; t < T_STEPS; t++) {
        // Load this time step's x (lanes 0..15; one component per element).
        if (lane < D_IN) {
            float4 xv;
            xv.x = x[((e0 + 0) * T_STEPS + t) * D_IN + lane];
            xv.y = x[((e0 + 1) * T_STEPS + t) * D_IN + lane];
            xv.z = x[((e0 + 2) * T_STEPS + t) * D_IN + lane];
            xv.w = x[((e0 + 3) * T_STEPS + t) * D_IN + lane];
            xsh[lane] = xv;
        }
        // cs_i = STEP * (dt1 - dt0) * DT_SCALER (redundant per lane, broadcast loads).
        float4 cs;
        {
            float2 d0 = dt2[(e0 + 0) * T_STEPS + t];
            float2 d1 = dt2[(e0 + 1) * T_STEPS + t];
            float2 d2 = dt2[(e0 + 2) * T_STEPS + t];
            float2 d3 = dt2[(e0 + 3) * T_STEPS + t];
            cs.x = STEP_F * ((d0.y - d0.x) * DT_SCALER_F);
            cs.y = STEP_F * ((d1.y - d1.x) * DT_SCALER_F);
            cs.z = STEP_F * ((d2.y - d2.x) * DT_SCALER_F);
            cs.w = STEP_F * ((d3.y - d3.x) * DT_SCALER_F);
        }
        __syncwarp();
        float4 y4 = xsh[0];   // y = x_i[:, 0]

#pragma unroll 1
        for (int s = 0; s < EULER_STEPS; s++) {
            float4 za = make_float4(b1a, b1a, b1a, b1a);
            float4 zb = make_float4(b1b, b1b, b1b, b1b);
            float4 ga = make_float4(b3a, b3a, b3a, b3a);
            float4 gb = make_float4(b3b, b3b, b3b, b3b);

            // z1 += x @ W1[:, :16]^T
#pragma unroll
            for (int k = 0; k < D_IN; k++) {
                float4 v = xsh[k];
                float2 w = sW1[k * 32 + lane];
                fma4(za, v, w.x);
                fma4(zb, v, w.y);
            }
            // Fused: z1 += h @ W1[:, 16:48]^T ; g_pre = h @ W3^T
#pragma unroll
            for (int k = 0; k < H_DIM; k++) {
                float4 v = hsh[k];
                float2 w = sW1[(D_IN + k) * 32 + lane];
                float2 u = sW3[k * 32 + lane];
                fma4(za, v, w.x);
                fma4(zb, v, w.y);
                fma4(ga, v, u.x);
                fma4(gb, v, u.y);
            }

            // z1 = tanh(.), publish to SMEM.
            float4 z0, z1v;
            z0.x = my_tanh(za.x);  z0.y = my_tanh(za.y);
            z0.z = my_tanh(za.z);  z0.w = my_tanh(za.w);
            z1v.x = my_tanh(zb.x); z1v.y = my_tanh(zb.y);
            z1v.z = my_tanh(zb.z); z1v.w = my_tanh(zb.w);
            zsh[lane] = z0;
            if (lane + 32 < HD_DIM) zsh[lane + 32] = z1v;

            // dy partial: tanh(g) @ W4^T (2 outputs per lane), butterfly reduce.
            float4 p;
            p.x = fmaf(my_tanh(ga.x), w4a, my_tanh(gb.x) * w4b);
            p.y = fmaf(my_tanh(ga.y), w4a, my_tanh(gb.y) * w4b);
            p.z = fmaf(my_tanh(ga.z), w4a, my_tanh(gb.z) * w4b);
            p.w = fmaf(my_tanh(ga.w), w4a, my_tanh(gb.w) * w4b);
#pragma unroll
            for (int off = 16; off > 0; off >>= 1) {
                p.x += __shfl_xor_sync(0xffffffffu, p.x, off);
                p.y += __shfl_xor_sync(0xffffffffu, p.y, off);
                p.z += __shfl_xor_sync(0xffffffffu, p.z, off);
                p.w += __shfl_xor_sync(0xffffffffu, p.w, off);
            }
            __syncwarp();   // z1 visible to all lanes

            // dh_pre = z1 @ W2^T (one output per lane)
            float4 dacc = make_float4(b2o, b2o, b2o, b2o);
#pragma unroll
            for (int j = 0; j < HD_DIM; j++) {
                float4 zv = zsh[j];
                float  w = sW2[j * 32 + lane];
                fma4(dacc, zv, w);
            }

            // Euler update: y += STEP*dy ; h += STEP*dh
            y4.x = fmaf(cs.x, p.x + b4v, y4.x);
            y4.y = fmaf(cs.y, p.y + b4v, y4.y);
            y4.z = fmaf(cs.z, p.z + b4v, y4.z);
            y4.w = fmaf(cs.w, p.w + b4v, y4.w);
            h4.x = fmaf(cs.x, my_tanh(dacc.x), h4.x);
            h4.y = fmaf(cs.y, my_tanh(dacc.y), h4.y);
            h4.z = fmaf(cs.z, my_tanh(dacc.z), h4.z);
            h4.w = fmaf(cs.w, my_tanh(dacc.w), h4.w);

            __syncwarp();   // all lanes done reading old h
            hsh[lane] = h4;
            __syncwarp();
        }

        // mu[e, t] = y. All lanes hold the full reduced y4; lanes 0..3 write.
        float yv = (lane == 0) ? y4.x : (lane == 1) ? y4.y : (lane == 2) ? y4.z : y4.w;
        if (lane < E_PER_WARP) {
            out[(e0 + lane) * T_STEPS + t] = yv;
        }
    }
}

extern "C" void kernel_launch(void* const* d_in, const int* in_sizes, int n_in,
                              void* d_out, int out_size) {
    (void)in_sizes; (void)n_in; (void)out_size;
    const float* dt = (const float*)d_in[0];
    const float* x  = (const float*)d_in[1];
    const float* W1 = (const float*)d_in[2];
    const float* b1 = (const float*)d_in[3];
    const float* W2 = (const float*)d_in[4];
    const float* b2 = (const float*)d_in[5];
    const float* W3 = (const float*)d_in[6];
    const float* b3 = (const float*)d_in[7];
    const float* W4 = (const float*)d_in[8];
    const float* b4 = (const float*)d_in[9];
    float* out = (float*)d_out;

    latentode2_kernel<<<GRID_BLOCKS, CTA_THREADS>>>(
        dt, x, W1, b1, W2, b2, W3, b3, W4, b4, out);
}